// round 5
// baseline (speedup 1.0000x reference)
#include <cuda_runtime.h>
#include <cstdint>

#define T_SEQ 128
#define BATCH 512
#define DIM   128
#define NQ    8
#define NCH   32   // 4 gates * 8 wires

typedef unsigned long long u64;

// dump target for lanes that don't own an output slot (never read)
__device__ float g_dump[64];

__device__ __forceinline__ float tanh_approx(float x) {
    float r;
    asm("tanh.approx.f32 %0, %1;" : "=f"(r) : "f"(x));
    return r;
}
__device__ __forceinline__ void ffma2(u64& acc, u64 a, u64 b) {
    asm("fma.rn.f32x2 %0, %1, %2, %0;" : "+l"(acc) : "l"(a), "l"(b));
}
__device__ __forceinline__ u64 pack2(float lo, float hi) {
    u64 r; asm("mov.b64 %0, {%1, %2};" : "=l"(r) : "f"(lo), "f"(hi)); return r;
}
__device__ __forceinline__ void unpack2(float& lo, float& hi, u64 v) {
    asm("mov.b64 {%0, %1}, %2;" : "=f"(lo), "=f"(hi) : "l"(v));
}
__device__ __forceinline__ void lds_v2u64(u64& a, u64& b, unsigned addr) {
    asm volatile("ld.shared.v2.u64 {%0, %1}, [%2];" : "=l"(a), "=l"(b) : "r"(addr));
}
__device__ __forceinline__ void cp_async16(unsigned smem, const void* g) {
    asm volatile("cp.async.ca.shared.global [%0], [%1], 16;" :: "r"(smem), "l"(g));
}
__device__ __forceinline__ void cp_commit() {
    asm volatile("cp.async.commit_group;");
}
__device__ __forceinline__ void cp_wait1() {
    asm volatile("cp.async.wait_group 1;");
}
__device__ __forceinline__ void cp_wait0() {
    asm volatile("cp.async.wait_group 0;");
}

// ---------------------------------------------------------------------------
// Fully fused QLSTM. One warp per batch row; lane = gate*8 + wire.
// The x-projection for step t+1 is computed DURING step t (off the recurrence
// chain): x row staged via one lane-distributed cp.async, dot via broadcast
// LDS.128 + packed FFMA2 against register-resident weight columns.
// Quantum layer (analytic): <Z_w> = prod_{k<=w} cos(phi_k) (w>=1),
//                           <Z_0> = prod_{k=1..7} cos(phi_k).
// ---------------------------------------------------------------------------
__global__ void __launch_bounds__(128) qlstm_fused(
    const float* __restrict__ x,
    const float* __restrict__ Wf, const float* __restrict__ bf, const float* __restrict__ thf,
    const float* __restrict__ Wi, const float* __restrict__ bi, const float* __restrict__ thi,
    const float* __restrict__ Wu, const float* __restrict__ bu, const float* __restrict__ thu,
    const float* __restrict__ Wo, const float* __restrict__ bo, const float* __restrict__ tho,
    float* __restrict__ out)
{
    __shared__ __align__(16) float xbuf[4][2][128];   // [warp][buf][float]

    const int lane = threadIdx.x & 31;
    const int warp = threadIdx.x >> 5;
    const int row  = blockIdx.x * 4 + warp;       // 0..511
    const int gate = lane >> 3;
    const int wire = lane & 7;
    const int base = lane & 24;                    // gate*8

    const float* Wg = (gate == 0) ? Wf : (gate == 1) ? Wi : (gate == 2) ? Wu : Wo;
    const float* bg = (gate == 0) ? bf : (gate == 1) ? bi : (gate == 2) ? bu : bo;
    const float* tg = (gate == 0) ? thf : (gate == 1) ? thi : (gate == 2) ? thu : tho;

    // x-part weight column for this lane's channel, packed as 64 f32x2 pairs
    u64 wx[64];
    #pragma unroll
    for (int i = 0; i < 64; ++i) {
        float a = Wg[(2 * i)     * NQ + wire];
        float b = Wg[(2 * i + 1) * NQ + wire];
        wx[i] = pack2(a, b);
    }

    // recurrent weight column
    float wh0 = Wg[(DIM + 0) * NQ + wire];
    float wh1 = Wg[(DIM + 1) * NQ + wire];
    float wh2 = Wg[(DIM + 2) * NQ + wire];
    float wh3 = Wg[(DIM + 3) * NQ + wire];
    float wh4 = Wg[(DIM + 4) * NQ + wire];
    float wh5 = Wg[(DIM + 5) * NQ + wire];
    float wh6 = Wg[(DIM + 6) * NQ + wire];
    float wh7 = Wg[(DIM + 7) * NQ + wire];

    const float cbias = bg[wire] + tg[wire];
    const bool  isU   = (gate == 2);
    const float aScl  = isU ? 1.0f : 0.5f;
    const float aMul  = isU ? 1.0f : 0.5f;
    const float aAdd  = isU ? 0.0f : 0.5f;

    const bool p0 = (wire & 1) != 0;
    const bool p1 = (wire & 2) != 0;
    const bool p2 = (wire & 4) != 0;

    float h0=0,h1=0,h2=0,h3=0,h4=0,h5=0,h6=0,h7=0;
    float cstate = 0.0f;

    // branch-free output pointer: real for lanes 0-7, dump (stride 0) otherwise
    float* st = (lane < 8) ? (out + (size_t)row * NQ + wire) : (g_dump + lane);
    const size_t sstr = (lane < 8) ? (size_t)(BATCH * NQ) : 0;

    // x row base for this warp's batch row; per-step stride = BATCH*DIM floats
    const float* xrow = x + (size_t)row * DIM + (size_t)lane * 4;
    const size_t xstep = (size_t)BATCH * DIM;

    const unsigned xs_base =
        (unsigned)__cvta_generic_to_shared(&xbuf[warp][0][0]) + (unsigned)(lane * 16);
    const unsigned xs_cons =
        (unsigned)__cvta_generic_to_shared(&xbuf[warp][0][0]);

    // Prologue: stage x[0] -> buf0, x[1] -> buf1
    cp_async16(xs_base,       xrow);             cp_commit();
    cp_async16(xs_base + 512, xrow + xstep);     cp_commit();
    cp_wait0();
    __syncwarp();

    // acc = dot(x[0], wx)
    u64 acc = 0ull;
    #pragma unroll
    for (int i = 0; i < 32; ++i) {
        u64 a, b;
        lds_v2u64(a, b, xs_cons + i * 16);
        ffma2(acc, a, wx[2 * i]);
        ffma2(acc, b, wx[2 * i + 1]);
    }

    const unsigned FULL = 0xffffffffu;

    #pragma unroll 1
    for (int t = 0; t < T_SEQ; ++t) {
        // z-base for this step from acc (dot of x[t], finished last iter)
        float zlo, zhi;
        unpack2(zlo, zhi, acc);
        float zb = (zlo + zhi) + cbias;

        // stage x[t+2] (clamped) into buf[t&1]; x[t+1] already in flight
        int ts = (t + 2 < T_SEQ) ? (t + 2) : (T_SEQ - 1);
        cp_async16(xs_base + (unsigned)((t & 1) * 512), xrow + (size_t)ts * xstep);
        cp_commit();
        cp_wait1();                 // x[t+1]'s group is now complete
        __syncwarp();

        // ---- recurrence chain ----
        float m0 = h0*wh0, m1 = h1*wh1, m2 = h2*wh2, m3 = h3*wh3;
        float m4 = h4*wh4, m5 = h5*wh5, m6 = h6*wh6, m7 = h7*wh7;
        float a01 = m0+m1, a23 = m2+m3, a45 = m4+m5, a67 = m6+m7;
        float z = ((a01+a23) + (a45+a67)) + zb;

        float c = __cosf(z);

        // ---- off-chain: dot(x[t+1], wx) into nacc (fills issue shadows) ----
        u64 nacc = 0ull;
        const unsigned cb = xs_cons + (unsigned)(((t + 1) & 1) * 512);
        #pragma unroll
        for (int i = 0; i < 32; ++i) {
            u64 xa, xb2;
            lds_v2u64(xa, xb2, cb + i * 16);
            ffma2(nacc, xa, wx[2 * i]);
            ffma2(nacc, xb2, wx[2 * i + 1]);
        }

        // allgather segment cosines
        float cc0 = __shfl_sync(FULL, c, base + 0);
        float cc1 = __shfl_sync(FULL, c, base + 1);
        float cc2 = __shfl_sync(FULL, c, base + 2);
        float cc3 = __shfl_sync(FULL, c, base + 3);
        float cc4 = __shfl_sync(FULL, c, base + 4);
        float cc5 = __shfl_sync(FULL, c, base + 5);
        float cc6 = __shfl_sync(FULL, c, base + 6);
        float cc7 = __shfl_sync(FULL, c, base + 7);

        // prefix products
        float m01 = cc0*cc1, m23 = cc2*cc3, m45 = cc4*cc5, m67 = cc6*cc7;
        float m0123 = m01*m23, m4567 = m45*m67;
        float P1 = m01;
        float P2 = m01*cc2;
        float P3 = m0123;
        float P4 = m0123*cc4;
        float P5 = m0123*m45;
        float P6 = m0123*(m45*cc6);
        float P7 = m0123*m4567;
        float E0 = (cc1*m23)*m4567;          // prod c1..c7

        // mux by wire bits
        float t0v = p0 ? P1 : E0;
        float t1v = p0 ? P3 : P2;
        float t2v = p0 ? P5 : P4;
        float t3v = p0 ? P7 : P6;
        float u0 = p1 ? t1v : t0v;
        float u1 = p1 ? t3v : t2v;
        float e  = p2 ? u1 : u0;             // <Z_wire>

        // activation: sigmoid via tanh for f,i,o; tanh for u
        float act = fmaf(aMul, tanh_approx(e * aScl), aAdd);

        // gather the four gate values of this wire
        float fv = __shfl_sync(FULL, act, wire);
        float iv = __shfl_sync(FULL, act, wire + 8);
        float gv = __shfl_sync(FULL, act, wire + 16);
        float ov = __shfl_sync(FULL, act, wire + 24);

        cstate   = fmaf(fv, cstate, iv * gv);
        float hw = ov * tanh_approx(cstate);

        *st = hw;           // branch-free (dump lanes write to scratch)
        st += sstr;

        // broadcast new hx (wire k lives on lane k)
        h0 = __shfl_sync(FULL, hw, 0);
        h1 = __shfl_sync(FULL, hw, 1);
        h2 = __shfl_sync(FULL, hw, 2);
        h3 = __shfl_sync(FULL, hw, 3);
        h4 = __shfl_sync(FULL, hw, 4);
        h5 = __shfl_sync(FULL, hw, 5);
        h6 = __shfl_sync(FULL, hw, 6);
        h7 = __shfl_sync(FULL, hw, 7);

        acc = nacc;
    }

    if (lane < 8) {
        const size_t outs_sz = (size_t)T_SEQ * BATCH * NQ;
        float hmy = (wire==0)?h0:(wire==1)?h1:(wire==2)?h2:(wire==3)?h3:
                    (wire==4)?h4:(wire==5)?h5:(wire==6)?h6:h7;
        out[outs_sz + (size_t)row * NQ + wire] = hmy;                          // final hx
        out[outs_sz + (size_t)BATCH * NQ + (size_t)row * NQ + wire] = cstate;  // final cx
    }
}

// ---------------------------------------------------------------------------
// Launch — single fused kernel
// ---------------------------------------------------------------------------
extern "C" void kernel_launch(void* const* d_in, const int* in_sizes, int n_in,
                              void* d_out, int out_size)
{
    const float* x   = (const float*)d_in[0];
    const float* Wf  = (const float*)d_in[1];
    const float* bf  = (const float*)d_in[2];
    const float* thf = (const float*)d_in[3];
    const float* Wi  = (const float*)d_in[4];
    const float* bi  = (const float*)d_in[5];
    const float* thi = (const float*)d_in[6];
    const float* Wu  = (const float*)d_in[7];
    const float* bu  = (const float*)d_in[8];
    const float* thu = (const float*)d_in[9];
    const float* Wo  = (const float*)d_in[10];
    const float* bo  = (const float*)d_in[11];
    const float* tho = (const float*)d_in[12];
    float* out = (float*)d_out;

    qlstm_fused<<<BATCH / 4, 128>>>(x,
                                    Wf, bf, thf, Wi, bi, thi,
                                    Wu, bu, thu, Wo, bo, tho, out);
}